// round 6
// baseline (speedup 1.0000x reference)
#include <cuda_runtime.h>
#include <cuda_fp16.h>
#include <cstdint>

// ============================================================
// Fused GRUCell, sm_103 base-PTX (ldmatrix + mma.sync.m16n8k16).
// Warp-specialized: 2 producer warps (LDG fp32 -> fp16 STS tiles),
// 6 consumer warps, each with a private 3-slot ring of fp16
// (x,hx) 32-row tiles, per-slot full/empty mbarriers.
// M=32 rows/warp halves B-weight smem traffic per row.
//   r = sig(x@Wir + hx@Whr + br); z = sig(x@Wiz + hx@Whz + bz)
//   n = tanh(x@Win + (r*hx)@Whn + bn); h = hx + z*(n - hx)
// B = 1048576, H = 64.
// ============================================================

#define DEV __device__ __forceinline__

static constexpr int NSLAB = 1048576 / 32;       // 32768 slabs of 32 rows

// ---- dynamic SMEM layout (bytes) ----
static constexpr int OFF_W    = 0;               // 6 x [64x64] f16 SW128 rows = 49152
static constexpr int OFF_BIAS = 49152;           // 3 x 64 fp32 = 768
static constexpr int OFF_MBAR = 50048;           // 18 slots x 16B (full@+0, empty@+8)
static constexpr int OFF_SLOT = 51200;           // slot tiles
static constexpr int SLOT_SZ  = 8192;            // x f16 32x128B + hx f16 32x128B
static constexpr int NSLOT    = 18;              // 6 consumers x 3-deep ring
static constexpr int SMEM_SZ  = OFF_SLOT + NSLOT * SLOT_SZ;   // 198656

DEV uint32_t sw(uint32_t o) { return o ^ ((o >> 3) & 0x70); }

DEV uint32_t s2u(const void* p) {
    uint32_t a;
    asm("{ .reg .u64 t; cvta.to.shared.u64 t, %1; cvt.u32.u64 %0, t; }" : "=r"(a) : "l"(p));
    return a;
}

#define MB_INIT(a, c)  asm volatile("mbarrier.init.shared.b64 [%0], %1;" :: "r"(a), "r"(c) : "memory")
#define MB_ARRIVE(a)   asm volatile("mbarrier.arrive.release.cta.shared::cta.b64 _, [%0];" :: "r"(a) : "memory")

#define MB_WAIT(addr, ph) do {                                                              \
    uint32_t _m = (addr), _p = (uint32_t)(ph), _d;                                          \
    asm volatile("{ .reg .pred p; mbarrier.try_wait.parity.acquire.cta.shared::cta.b64 p, [%1], %2; selp.b32 %0,1,0,p; }" \
                 : "=r"(_d) : "r"(_m), "r"(_p) : "memory");                                 \
    while (!_d) {                                                                           \
        asm volatile("{ .reg .pred p; mbarrier.try_wait.parity.acquire.cta.shared::cta.b64 p, [%1], %2, 0x989680; selp.b32 %0,1,0,p; }" \
                     : "=r"(_d) : "r"(_m), "r"(_p) : "memory");                             \
    }                                                                                       \
} while (0)

DEV void ldsm4(uint32_t& d0, uint32_t& d1, uint32_t& d2, uint32_t& d3, uint32_t a) {
    asm volatile("ldmatrix.sync.aligned.m8n8.x4.shared.b16 {%0,%1,%2,%3}, [%4];"
                 : "=r"(d0), "=r"(d1), "=r"(d2), "=r"(d3) : "r"(a));
}
DEV void ldsm4t(uint32_t& d0, uint32_t& d1, uint32_t& d2, uint32_t& d3, uint32_t a) {
    asm volatile("ldmatrix.sync.aligned.m8n8.x4.trans.shared.b16 {%0,%1,%2,%3}, [%4];"
                 : "=r"(d0), "=r"(d1), "=r"(d2), "=r"(d3) : "r"(a));
}

DEV void mma4(float* c, const uint32_t* a, uint32_t b0, uint32_t b1) {
    asm volatile(
        "mma.sync.aligned.m16n8k16.row.col.f32.f16.f16.f32 "
        "{%0,%1,%2,%3}, {%4,%5,%6,%7}, {%8,%9}, {%0,%1,%2,%3};"
        : "+f"(c[0]), "+f"(c[1]), "+f"(c[2]), "+f"(c[3])
        : "r"(a[0]), "r"(a[1]), "r"(a[2]), "r"(a[3]), "r"(b0), "r"(b1));
}

// single-MUFU activations
DEV float tanh_ap(float x) {
    float r;
    asm("tanh.approx.f32 %0, %1;" : "=f"(r) : "f"(x));
    return r;
}
DEV float sigm(float x) { return fmaf(0.5f, tanh_ap(0.5f * x), 0.5f); }

DEV uint32_t packh2(float a, float b) {
    __half2 h = __floats2half2_rn(a, b);
    return *(uint32_t*)&h;
}

// GEMM accumulate: acc[2][8][4] += A(32x64 reg frags) @ W(64x64 f16 smem)
DEV void gemm2(float acc[2][8][4], const uint32_t af[2][4][4], uint32_t wbase, int laneB) {
    #pragma unroll
    for (int kb = 0; kb < 4; kb++) {
        #pragma unroll
        for (int nbp = 0; nbp < 4; nbp++) {
            uint32_t b0, b1, b2, b3;
            ldsm4t(b0, b1, b2, b3, wbase + sw((uint32_t)(laneB + kb * 2048 + nbp * 32)));
            #pragma unroll
            for (int mb = 0; mb < 2; mb++) {
                mma4(acc[mb][2 * nbp],     af[mb][kb], b0, b1);
                mma4(acc[mb][2 * nbp + 1], af[mb][kb], b2, b3);
            }
        }
    }
}

// Build A-fragments for a 32x64 fp16 tile via ldmatrix (8 x4-loads).
DEV void build_af2(uint32_t af[2][4][4], uint32_t tile, int lane) {
    int rowA  = lane & 15;
    int colAB = (lane >> 4) * 16;   // byte offset within 16-halves group
    #pragma unroll
    for (int mb = 0; mb < 2; mb++) {
        #pragma unroll
        for (int kb = 0; kb < 4; kb++) {
            uint32_t a = tile + sw((uint32_t)((mb * 16 + rowA) * 128 + kb * 32 + colAB));
            ldsm4(af[mb][kb][0], af[mb][kb][1], af[mb][kb][2], af[mb][kb][3], a);
        }
    }
}

// Producer: fill one slot with slab g (fp32 -> fp16, SW128 layout).
DEV void fill_slot(const float* __restrict__ x, const float* __restrict__ hx,
                   char* sm, int slot, long g, int lane) {
    const float4* xs = ((const float4*)x)  + (size_t)g * 512;   // 32 rows x 16 float4
    const float4* hs = ((const float4*)hx) + (size_t)g * 512;
    char* xb = sm + OFF_SLOT + slot * SLOT_SZ;
    char* hb = xb + 4096;
    #pragma unroll
    for (int half = 0; half < 2; half++) {
        float4 vx[8], vh[8];
        #pragma unroll
        for (int j = 0; j < 8; j++) {
            int idx = lane + (half * 8 + j) * 32;
            vx[j] = xs[idx];
            vh[j] = hs[idx];
        }
        #pragma unroll
        for (int j = 0; j < 8; j++) {
            int idx = lane + (half * 8 + j) * 32;
            int row = idx >> 4, c4 = idx & 15;
            uint32_t so = sw((uint32_t)(row * 128 + c4 * 8));
            *(uint2*)(xb + so) = make_uint2(packh2(vx[j].x, vx[j].y), packh2(vx[j].z, vx[j].w));
            *(uint2*)(hb + so) = make_uint2(packh2(vh[j].x, vh[j].y), packh2(vh[j].z, vh[j].w));
        }
    }
}

__global__ void __launch_bounds__(256, 1) gru_kernel(
    const float* __restrict__ x,    const float* __restrict__ hx,
    const float* __restrict__ w_ir, const float* __restrict__ w_hr,
    const float* __restrict__ w_iz, const float* __restrict__ w_hz,
    const float* __restrict__ w_in, const float* __restrict__ w_hn,
    const float* __restrict__ b_r,  const float* __restrict__ b_z,
    const float* __restrict__ b_n,  float* __restrict__ out)
{
    extern __shared__ char sm[];
    const uint32_t SB = s2u(sm);
    const int tid  = threadIdx.x;
    const int lane = tid & 31;
    const int wid  = tid >> 5;

    // ---- one-time: weights -> f16 SMEM ([k][n] rows of 128B, SW128), biases ----
    {
        const float* ws[6] = {w_ir, w_hr, w_iz, w_hz, w_in, w_hn};
        #pragma unroll 1
        for (int g = 0; g < 6; g++) {
            const float* w = ws[g];
            for (int i = tid; i < 4096; i += 256) {
                int k = i >> 6, n = i & 63;
                *(__half*)(sm + OFF_W + g * 8192 + sw((uint32_t)(k * 128 + n * 2))) =
                    __float2half_rn(w[i]);
            }
        }
        if (tid < 64) {
            float* bs = (float*)(sm + OFF_BIAS);
            bs[tid]       = b_r[tid];
            bs[64 + tid]  = b_z[tid];
            bs[128 + tid] = b_n[tid];
        }
        if (tid == 0) {
            for (int s = 0; s < NSLOT; s++) {
                MB_INIT(SB + OFF_MBAR + s * 16,     32);  // full
                MB_INIT(SB + OFF_MBAR + s * 16 + 8, 32);  // empty
            }
        }
    }
    __syncthreads();   // only CTA-wide barrier

    const long stride = 6L * gridDim.x;

    if (wid >= 6) {
        // ================= producer warps (6,7): 3 consumers each =================
        const int p = wid - 6;
        for (int kc = 0; ; kc++) {
            bool any = false;
            #pragma unroll 1
            for (int ci = 0; ci < 3; ci++) {
                const int c = p * 3 + ci;
                const long g = (long)blockIdx.x * 6 + c + (long)kc * stride;
                if (g >= NSLAB) continue;
                any = true;
                const int slot = c * 3 + kc % 3;
                if (kc >= 3) MB_WAIT(SB + OFF_MBAR + slot * 16 + 8, ((kc / 3) - 1) & 1);
                fill_slot(x, hx, sm, slot, g, lane);
                MB_ARRIVE(SB + OFF_MBAR + slot * 16);     // full (count 32)
            }
            if (!any) break;
        }
        return;
    }

    // ================= consumer warps (0-5) =================
    const int laneB = (lane & 15) * 128 + ((lane >> 4) << 4);  // ldmatrix B lane offset
    const int q2    = (lane & 3) * 2;
    const int grow  = lane >> 2;

    int k = 0;
    for (long g = (long)blockIdx.x * 6 + wid; g < NSLAB; g += stride, k++) {
        const int slot = wid * 3 + k % 3;
        const uint32_t fullb = SB + OFF_MBAR + slot * 16;
        MB_WAIT(fullb, (k / 3) & 1);

        const uint32_t xt = SB + OFF_SLOT + slot * SLOT_SZ;
        const uint32_t ht = xt + 4096;
        const char* htc = sm + OFF_SLOT + slot * SLOT_SZ + 4096;

        // ---- A fragments ----
        uint32_t xf[2][4][4], hf[2][4][4];
        build_af2(xf, xt, lane);
        build_af2(hf, ht, lane);

        // ---- r, z ----
        float rc[2][8][4], zc[2][8][4];
        #pragma unroll
        for (int nb = 0; nb < 8; nb++) {
            float2 br = *(float2*)(sm + OFF_BIAS       + (nb * 8 + q2) * 4);
            float2 bz = *(float2*)(sm + OFF_BIAS + 256 + (nb * 8 + q2) * 4);
            #pragma unroll
            for (int mb = 0; mb < 2; mb++) {
                rc[mb][nb][0] = br.x; rc[mb][nb][1] = br.y;
                rc[mb][nb][2] = br.x; rc[mb][nb][3] = br.y;
                zc[mb][nb][0] = bz.x; zc[mb][nb][1] = bz.y;
                zc[mb][nb][2] = bz.x; zc[mb][nb][3] = bz.y;
            }
        }
        gemm2(rc, xf, SB + OFF_W,            laneB);
        gemm2(rc, hf, SB + OFF_W + 1 * 8192, laneB);
        gemm2(zc, xf, SB + OFF_W + 2 * 8192, laneB);
        gemm2(zc, hf, SB + OFF_W + 3 * 8192, laneB);

        // ---- rh = sigmoid(rc) * hx (fp16) -> A-fragments in registers ----
        uint32_t rhf[2][4][4];
        #pragma unroll
        for (int mb = 0; mb < 2; mb++) {
            const char* r0 = htc;  // row base computed per access
            #pragma unroll
            for (int kb = 0; kb < 4; kb++) {
                int cb = kb * 32 + q2 * 2;                       // byte col offset
                __half2 ha = *(const __half2*)(r0 + sw((uint32_t)((mb*16 + grow)     * 128 + cb)));
                __half2 hb = *(const __half2*)(r0 + sw((uint32_t)((mb*16 + grow + 8) * 128 + cb)));
                __half2 hc = *(const __half2*)(r0 + sw((uint32_t)((mb*16 + grow)     * 128 + cb + 16)));
                __half2 hd = *(const __half2*)(r0 + sw((uint32_t)((mb*16 + grow + 8) * 128 + cb + 16)));
                const float* ce = rc[mb][2 * kb];
                const float* co = rc[mb][2 * kb + 1];
                __half2 s0 = __floats2half2_rn(sigm(ce[0]), sigm(ce[1]));
                __half2 s1 = __floats2half2_rn(sigm(ce[2]), sigm(ce[3]));
                __half2 s2 = __floats2half2_rn(sigm(co[0]), sigm(co[1]));
                __half2 s3 = __floats2half2_rn(sigm(co[2]), sigm(co[3]));
                __half2 m0 = __hmul2(s0, ha), m1 = __hmul2(s1, hb);
                __half2 m2 = __hmul2(s2, hc), m3 = __hmul2(s3, hd);
                rhf[mb][kb][0] = *(uint32_t*)&m0;
                rhf[mb][kb][1] = *(uint32_t*)&m1;
                rhf[mb][kb][2] = *(uint32_t*)&m2;
                rhf[mb][kb][3] = *(uint32_t*)&m3;
            }
        }

        // ---- n = x@Win + rh@Whn + bn ----
        float nc[2][8][4];
        #pragma unroll
        for (int nb = 0; nb < 8; nb++) {
            float2 bn = *(float2*)(sm + OFF_BIAS + 512 + (nb * 8 + q2) * 4);
            #pragma unroll
            for (int mb = 0; mb < 2; mb++) {
                nc[mb][nb][0] = bn.x; nc[mb][nb][1] = bn.y;
                nc[mb][nb][2] = bn.x; nc[mb][nb][3] = bn.y;
            }
        }
        gemm2(nc, xf,  SB + OFF_W + 4 * 8192, laneB);
        gemm2(nc, rhf, SB + OFF_W + 5 * 8192, laneB);

        // ---- epilogue: h = hx + z*(n - hx), hx fp16 from tile ----
        #pragma unroll
        for (int mb = 0; mb < 2; mb++) {
            const long rg = g * 32 + mb * 16 + grow;
            #pragma unroll
            for (int nb = 0; nb < 8; nb++) {
                int cb = (nb * 8 + q2) * 2;                      // byte col offset
                __half2 ha = *(const __half2*)(htc + sw((uint32_t)((mb*16 + grow)     * 128 + cb)));
                __half2 hb = *(const __half2*)(htc + sw((uint32_t)((mb*16 + grow + 8) * 128 + cb)));
                float2 a = __half22float2(ha);
                float2 b = __half22float2(hb);
                const float* zz = zc[mb][nb];
                const float* nn = nc[mb][nb];
                float z0 = sigm(zz[0]), z1 = sigm(zz[1]);
                float z2 = sigm(zz[2]), z3 = sigm(zz[3]);
                float n0 = tanh_ap(nn[0]), n1 = tanh_ap(nn[1]);
                float n2 = tanh_ap(nn[2]), n3 = tanh_ap(nn[3]);
                *(float2*)(out + rg * 64 + (nb * 8 + q2)) =
                    make_float2(fmaf(z0, n0 - a.x, a.x), fmaf(z1, n1 - a.y, a.y));
                *(float2*)(out + (rg + 8) * 64 + (nb * 8 + q2)) =
                    make_float2(fmaf(z2, n2 - b.x, b.x), fmaf(z3, n3 - b.y, b.y));
            }
        }

        MB_ARRIVE(fullb + 8);   // empty (count 32)
    }
}

extern "C" void kernel_launch(void* const* d_in, const int* in_sizes, int n_in,
                              void* d_out, int out_size) {
    int sms = 0;
    cudaDeviceGetAttribute(&sms, cudaDevAttrMultiProcessorCount, 0);
    if (sms <= 0) sms = 148;
    cudaFuncSetAttribute(gru_kernel, cudaFuncAttributeMaxDynamicSharedMemorySize, SMEM_SZ);
    gru_kernel<<<sms, 256, SMEM_SZ>>>(
        (const float*)d_in[0], (const float*)d_in[1],
        (const float*)d_in[2], (const float*)d_in[3],
        (const float*)d_in[4], (const float*)d_in[5],
        (const float*)d_in[6], (const float*)d_in[7],
        (const float*)d_in[8], (const float*)d_in[9],
        (const float*)d_in[10], (float*)d_out);
}

// round 7
// speedup vs baseline: 1.0718x; 1.0718x over previous
#include <cuda_runtime.h>
#include <cuda_fp16.h>
#include <cstdint>

// ============================================================
// Fused GRUCell, sm_103 base-PTX (ldmatrix + mma.sync.m16n8k16).
// ZERO input staging: A-fragments (x, hx) are built directly from
// global memory with sector-efficient LDG.64; hx fragments are
// reused for r*hx and the epilogue. SMEM holds only the six fp16
// weight matrices (ldmatrix.trans source) + biases.
//   r = sig(x@Wir + hx@Whr + br); z = sig(x@Wiz + hx@Whz + bz)
//   n = tanh(x@Win + (r*hx)@Whn + bn); h = hx + z*(n - hx)
// B = 1048576, H = 64. M = 32 rows per warp per iteration.
// ============================================================

#define DEV __device__ __forceinline__

static constexpr int NSLAB = 1048576 / 32;       // 32768 slabs of 32 rows

// ---- dynamic SMEM layout (bytes) ----
static constexpr int OFF_W    = 0;               // 6 x [64x64] f16 SW128 rows = 49152
static constexpr int OFF_BIAS = 49152;           // 3 x 64 fp32 = 768
static constexpr int SMEM_SZ  = 50176;

DEV uint32_t sw(uint32_t o) { return o ^ ((o >> 3) & 0x70); }

DEV uint32_t s2u(const void* p) {
    uint32_t a;
    asm("{ .reg .u64 t; cvta.to.shared.u64 t, %1; cvt.u32.u64 %0, t; }" : "=r"(a) : "l"(p));
    return a;
}

DEV void ldsm4t(uint32_t& d0, uint32_t& d1, uint32_t& d2, uint32_t& d3, uint32_t a) {
    asm volatile("ldmatrix.sync.aligned.m8n8.x4.trans.shared.b16 {%0,%1,%2,%3}, [%4];"
                 : "=r"(d0), "=r"(d1), "=r"(d2), "=r"(d3) : "r"(a));
}

DEV void mma4(float* c, const uint32_t* a, uint32_t b0, uint32_t b1) {
    asm volatile(
        "mma.sync.aligned.m16n8k16.row.col.f32.f16.f16.f32 "
        "{%0,%1,%2,%3}, {%4,%5,%6,%7}, {%8,%9}, {%0,%1,%2,%3};"
        : "+f"(c[0]), "+f"(c[1]), "+f"(c[2]), "+f"(c[3])
        : "r"(a[0]), "r"(a[1]), "r"(a[2]), "r"(a[3]), "r"(b0), "r"(b1));
}

// single-MUFU activations
DEV float tanh_ap(float x) {
    float r;
    asm("tanh.approx.f32 %0, %1;" : "=f"(r) : "f"(x));
    return r;
}
DEV float sigm(float x) { return fmaf(0.5f, tanh_ap(0.5f * x), 0.5f); }

DEV uint32_t packh2(float a, float b) {
    __half2 h = __floats2half2_rn(a, b);
    return *(uint32_t*)&h;
}

// GEMM accumulate: acc[2][8][4] += A(32x64 reg frags) @ W(64x64 f16 smem)
DEV void gemm2(float acc[2][8][4], const uint32_t af[2][4][4], uint32_t wbase, int laneB) {
    #pragma unroll
    for (int kb = 0; kb < 4; kb++) {
        #pragma unroll
        for (int nbp = 0; nbp < 4; nbp++) {
            uint32_t b0, b1, b2, b3;
            ldsm4t(b0, b1, b2, b3, wbase + sw((uint32_t)(laneB + kb * 2048 + nbp * 32)));
            #pragma unroll
            for (int mb = 0; mb < 2; mb++) {
                mma4(acc[mb][2 * nbp],     af[mb][kb], b0, b1);
                mma4(acc[mb][2 * nbp + 1], af[mb][kb], b2, b3);
            }
        }
    }
}

__global__ void __launch_bounds__(256, 1) gru_kernel(
    const float* __restrict__ x,    const float* __restrict__ hx,
    const float* __restrict__ w_ir, const float* __restrict__ w_hr,
    const float* __restrict__ w_iz, const float* __restrict__ w_hz,
    const float* __restrict__ w_in, const float* __restrict__ w_hn,
    const float* __restrict__ b_r,  const float* __restrict__ b_z,
    const float* __restrict__ b_n,  float* __restrict__ out)
{
    extern __shared__ char sm[];
    const uint32_t SB = s2u(sm);
    const int tid  = threadIdx.x;
    const int lane = tid & 31;
    const int wid  = tid >> 5;

    // ---- one-time: weights -> f16 SMEM ([k][n] rows of 128B, SW128), biases ----
    {
        const float* ws[6] = {w_ir, w_hr, w_iz, w_hz, w_in, w_hn};
        #pragma unroll 1
        for (int g = 0; g < 6; g++) {
            const float* w = ws[g];
            for (int i = tid; i < 4096; i += 256) {
                int k = i >> 6, n = i & 63;
                *(__half*)(sm + OFF_W + g * 8192 + sw((uint32_t)(k * 128 + n * 2))) =
                    __float2half_rn(w[i]);
            }
        }
        if (tid < 64) {
            float* bs = (float*)(sm + OFF_BIAS);
            bs[tid]       = b_r[tid];
            bs[64 + tid]  = b_z[tid];
            bs[128 + tid] = b_n[tid];
        }
    }
    __syncthreads();   // only CTA-wide barrier in the kernel

    const int laneB = (lane & 15) * 128 + ((lane >> 4) << 4);  // ldmatrix B lane offset
    const int q2    = (lane & 3) * 2;
    const int grow  = lane >> 2;

    const long stride = 8L * gridDim.x;

    for (long g = (long)blockIdx.x * 8 + wid; g < NSLAB; g += stride) {
        // ---- build A-fragments for x and hx straight from gmem ----
        // frag a0:(grow, c..c+1) a1:(grow+8, c..) a2:(grow, c+8..) a3:(grow+8, c+8..)
        // with c = kb*16 + q2. Each LDG.64 instruction covers 8 full 32B sectors.
        uint32_t xf[2][4][4], hf[2][4][4];
        {
            const float* xb = x  + (size_t)g * 2048;   // 32 rows x 64
            const float* hb = hx + (size_t)g * 2048;
            #pragma unroll
            for (int mb = 0; mb < 2; mb++) {
                const float* xr0 = xb + (mb * 16 + grow) * 64;
                const float* xr8 = xr0 + 8 * 64;
                const float* hr0 = hb + (mb * 16 + grow) * 64;
                const float* hr8 = hr0 + 8 * 64;
                #pragma unroll
                for (int kb = 0; kb < 4; kb++) {
                    int c = kb * 16 + q2;
                    float2 v0 = *(const float2*)(xr0 + c);
                    float2 v1 = *(const float2*)(xr8 + c);
                    float2 v2 = *(const float2*)(xr0 + c + 8);
                    float2 v3 = *(const float2*)(xr8 + c + 8);
                    xf[mb][kb][0] = packh2(v0.x, v0.y);
                    xf[mb][kb][1] = packh2(v1.x, v1.y);
                    xf[mb][kb][2] = packh2(v2.x, v2.y);
                    xf[mb][kb][3] = packh2(v3.x, v3.y);
                    float2 u0 = *(const float2*)(hr0 + c);
                    float2 u1 = *(const float2*)(hr8 + c);
                    float2 u2 = *(const float2*)(hr0 + c + 8);
                    float2 u3 = *(const float2*)(hr8 + c + 8);
                    hf[mb][kb][0] = packh2(u0.x, u0.y);
                    hf[mb][kb][1] = packh2(u1.x, u1.y);
                    hf[mb][kb][2] = packh2(u2.x, u2.y);
                    hf[mb][kb][3] = packh2(u3.x, u3.y);
                }
            }
        }

        // ---- r = sig(x@Wir + hx@Whr + br) (accumulators bias-initialized) ----
        float rc[2][8][4];
        #pragma unroll
        for (int nb = 0; nb < 8; nb++) {
            float2 br = *(float2*)(sm + OFF_BIAS + (nb * 8 + q2) * 4);
            #pragma unroll
            for (int mb = 0; mb < 2; mb++) {
                rc[mb][nb][0] = br.x; rc[mb][nb][1] = br.y;
                rc[mb][nb][2] = br.x; rc[mb][nb][3] = br.y;
            }
        }
        gemm2(rc, xf, SB + OFF_W,            laneB);
        gemm2(rc, hf, SB + OFF_W + 1 * 8192, laneB);

        // ---- rh = sigmoid(rc) * hx -> A-fragments (hx from hf, fp16) ----
        // identity: c-frag(nb=2kb) -> a0,a1 ; c-frag(nb=2kb+1) -> a2,a3
        uint32_t rhf[2][4][4];
        #pragma unroll
        for (int mb = 0; mb < 2; mb++) {
            #pragma unroll
            for (int kb = 0; kb < 4; kb++) {
                const float* ce = rc[mb][2 * kb];
                const float* co = rc[mb][2 * kb + 1];
                __half2 s0 = __floats2half2_rn(sigm(ce[0]), sigm(ce[1]));
                __half2 s1 = __floats2half2_rn(sigm(ce[2]), sigm(ce[3]));
                __half2 s2 = __floats2half2_rn(sigm(co[0]), sigm(co[1]));
                __half2 s3 = __floats2half2_rn(sigm(co[2]), sigm(co[3]));
                __half2 m0 = __hmul2(s0, *(const __half2*)&hf[mb][kb][0]);
                __half2 m1 = __hmul2(s1, *(const __half2*)&hf[mb][kb][1]);
                __half2 m2 = __hmul2(s2, *(const __half2*)&hf[mb][kb][2]);
                __half2 m3 = __hmul2(s3, *(const __half2*)&hf[mb][kb][3]);
                rhf[mb][kb][0] = *(uint32_t*)&m0;
                rhf[mb][kb][1] = *(uint32_t*)&m1;
                rhf[mb][kb][2] = *(uint32_t*)&m2;
                rhf[mb][kb][3] = *(uint32_t*)&m3;
            }
        }

        // ---- n = x@Win + rh@Whn + bn  (rc dead -> register reuse) ----
        float nc[2][8][4];
        #pragma unroll
        for (int nb = 0; nb < 8; nb++) {
            float2 bn = *(float2*)(sm + OFF_BIAS + 512 + (nb * 8 + q2) * 4);
            #pragma unroll
            for (int mb = 0; mb < 2; mb++) {
                nc[mb][nb][0] = bn.x; nc[mb][nb][1] = bn.y;
                nc[mb][nb][2] = bn.x; nc[mb][nb][3] = bn.y;
            }
        }
        gemm2(nc, xf,  SB + OFF_W + 4 * 8192, laneB);
        gemm2(nc, rhf, SB + OFF_W + 5 * 8192, laneB);

        // ---- z = sig(x@Wiz + hx@Whz + bz)  (rhf dead) ----
        float zc[2][8][4];
        #pragma unroll
        for (int nb = 0; nb < 8; nb++) {
            float2 bz = *(float2*)(sm + OFF_BIAS + 256 + (nb * 8 + q2) * 4);
            #pragma unroll
            for (int mb = 0; mb < 2; mb++) {
                zc[mb][nb][0] = bz.x; zc[mb][nb][1] = bz.y;
                zc[mb][nb][2] = bz.x; zc[mb][nb][3] = bz.y;
            }
        }
        gemm2(zc, xf, SB + OFF_W + 2 * 8192, laneB);
        gemm2(zc, hf, SB + OFF_W + 3 * 8192, laneB);

        // ---- epilogue: h = hx + z*(n - hx); hx from hf fragments ----
        #pragma unroll
        for (int mb = 0; mb < 2; mb++) {
            const long rg = g * 32 + mb * 16 + grow;
            #pragma unroll
            for (int nb = 0; nb < 8; nb++) {
                int kb = nb >> 1, e = (nb & 1) * 2;
                float2 a = __half22float2(*(const __half2*)&hf[mb][kb][e]);     // row grow
                float2 b = __half22float2(*(const __half2*)&hf[mb][kb][e + 1]); // row grow+8
                const float* zz = zc[mb][nb];
                const float* nn = nc[mb][nb];
                float z0 = sigm(zz[0]), z1 = sigm(zz[1]);
                float z2 = sigm(zz[2]), z3 = sigm(zz[3]);
                float n0 = tanh_ap(nn[0]), n1 = tanh_ap(nn[1]);
                float n2 = tanh_ap(nn[2]), n3 = tanh_ap(nn[3]);
                *(float2*)(out + rg * 64 + (nb * 8 + q2)) =
                    make_float2(fmaf(z0, n0 - a.x, a.x), fmaf(z1, n1 - a.y, a.y));
                *(float2*)(out + (rg + 8) * 64 + (nb * 8 + q2)) =
                    make_float2(fmaf(z2, n2 - b.x, b.x), fmaf(z3, n3 - b.y, b.y));
            }
        }
    }
}

extern "C" void kernel_launch(void* const* d_in, const int* in_sizes, int n_in,
                              void* d_out, int out_size) {
    int sms = 0;
    cudaDeviceGetAttribute(&sms, cudaDevAttrMultiProcessorCount, 0);
    if (sms <= 0) sms = 148;
    cudaFuncSetAttribute(gru_kernel, cudaFuncAttributeMaxDynamicSharedMemorySize, SMEM_SZ);
    gru_kernel<<<sms, 256, SMEM_SZ>>>(
        (const float*)d_in[0], (const float*)d_in[1],
        (const float*)d_in[2], (const float*)d_in[3],
        (const float*)d_in[4], (const float*)d_in[5],
        (const float*)d_in[6], (const float*)d_in[7],
        (const float*)d_in[8], (const float*)d_in[9],
        (const float*)d_in[10], (float*)d_out);
}